// round 1
// baseline (speedup 1.0000x reference)
#include <cuda_runtime.h>
#include <cstdint>

// Problem shape (fixed by reference): B=32, C=256, H=64, W=64
// in:  d_in[0] = data_in   [B,C,H,W] f32  (33,554,432 elems)
//      d_in[1] = td_energy [C]       f32  (256)
//      d_in[2] = td_hist   [100,100] f32  (10,000)
// out: [ data_in copy | energy+meanabs | hist+1 ]  (f32)

static constexpr int B = 32;
static constexpr int C = 256;
static constexpr int HW = 64 * 64;          // 4096 floats per plane
static constexpr int PLANES = B * C;        // 8192
static constexpr long long N_DATA = (long long)PLANES * HW;  // 33,554,432
static constexpr float INV_N = 1.0f / (float)(B * HW);       // 1/131072

__global__ void init_small(const float* __restrict__ td_energy,
                           const float* __restrict__ td_hist,
                           float* __restrict__ out_energy,
                           float* __restrict__ out_hist) {
    int i = blockIdx.x * blockDim.x + threadIdx.x;
    if (i < C)      out_energy[i] = td_energy[i];
    if (i < 10000)  out_hist[i]   = td_hist[i] + 1.0f;
}

// One block per (b,c) plane: copy 4096 floats (float4 vectorized) and
// accumulate sum(|x|); scaled partial atomically added to out_energy[c].
__global__ __launch_bounds__(256) void copy_reduce(
    const float4* __restrict__ in,
    float4* __restrict__ out,
    float* __restrict__ out_energy) {

    const int plane = blockIdx.x;           // b*C + c
    const int c = plane & (C - 1);
    const size_t base = (size_t)plane * (HW / 4);   // float4 units

    const float4* src = in + base;
    float4* dst = out + base;

    float s = 0.0f;
#pragma unroll
    for (int i = 0; i < 4; i++) {
        float4 v = src[threadIdx.x + i * 256];
        dst[threadIdx.x + i * 256] = v;
        s += fabsf(v.x) + fabsf(v.y) + fabsf(v.z) + fabsf(v.w);
    }

    // warp reduce
#pragma unroll
    for (int o = 16; o > 0; o >>= 1)
        s += __shfl_xor_sync(0xffffffffu, s, o);

    __shared__ float ws[8];
    if ((threadIdx.x & 31) == 0) ws[threadIdx.x >> 5] = s;
    __syncthreads();

    if (threadIdx.x < 8) {
        s = ws[threadIdx.x];
#pragma unroll
        for (int o = 4; o > 0; o >>= 1)
            s += __shfl_xor_sync(0xffu, s, o);
        if (threadIdx.x == 0)
            atomicAdd(&out_energy[c], s * INV_N);
    }
}

extern "C" void kernel_launch(void* const* d_in, const int* in_sizes, int n_in,
                              void* d_out, int out_size) {
    const float* data_in   = (const float*)d_in[0];
    const float* td_energy = (const float*)d_in[1];
    const float* td_hist   = (const float*)d_in[2];

    float* out      = (float*)d_out;
    float* out_energy = out + N_DATA;
    float* out_hist   = out_energy + C;

    // 1) initialize energy (base values) and hist (+1). Must precede atomics;
    //    same-stream ordering guarantees that under graph capture.
    init_small<<<(10000 + 255) / 256, 256>>>(td_energy, td_hist,
                                             out_energy, out_hist);

    // 2) fused copy + per-channel |x| reduction
    copy_reduce<<<PLANES, 256>>>((const float4*)data_in, (float4*)out,
                                 out_energy);
}